// round 3
// baseline (speedup 1.0000x reference)
#include <cuda_runtime.h>

// LocallyConnectedLinear: out[b,h,w,o] = sum_k xpatch[b,h,w,k] * W[h,w,k,o]
// x:  [8, 32, 32, 64]  f32   (NHWC)
// W:  [30, 30, 576, 64] f32  (k = c*9 + kh*3 + kw ; C slowest)
// out:[8, 30, 30, 64]  f32
//
// HBM-bound on the 132.7 MB weight stream. One CTA per spatial location.
// R1: thread=(b,o4) read each weight 8x -> L1-bound (53.7us).
// R2: thread=(kslice,o4), weights read once, 8 batch accs in regs (31.2us,
//     DRAM 58%). Issue-limited: 32 scalar FFMA per 512B of weights.
// R3: fma.rn.f32x2 (FFMA2) halves FMA instruction count; x staged
//     pre-duplicated in smem so no per-k packing is needed.

#define H_OUT 30
#define W_OUT 30
#define H_IN  32
#define W_IN  32
#define C_IN  64
#define C_OUT 64
#define KK    576   // 64 * 3 * 3
#define BATCH 8
#define NTHREADS 128
#define NSLICE 8
#define KPS    72   // KK / NSLICE

typedef unsigned long long u64;

__device__ __forceinline__ u64 fma2(u64 a, u64 b, u64 c) {
    u64 d;
    asm("fma.rn.f32x2 %0, %1, %2, %3;" : "=l"(d) : "l"(a), "l"(b), "l"(c));
    return d;
}
__device__ __forceinline__ u64 add2(u64 a, u64 b) {
    u64 d;
    asm("add.rn.f32x2 %0, %1, %2;" : "=l"(d) : "l"(a), "l"(b));
    return d;
}

__global__ __launch_bounds__(NTHREADS, 6)
void lc_kernel(const float* __restrict__ x,
               const float* __restrict__ w,
               float* __restrict__ out)
{
    // Phase 1: xs2[k][b] = (v, v) duplicated pairs, KK x 8 float2 = 36 KB.
    // Phase 2 (aliased): reduction buffer [8][16][9] ulonglong2 = 18 KB.
    __shared__ __align__(16) float2 xs2[KK * BATCH];

    const int loc = blockIdx.x;          // 0..899
    const int h   = loc / W_OUT;
    const int wo  = loc - h * W_OUT;
    const int tid = threadIdx.x;

    // ---- Stage im2col patch, duplicated: xs2[k*8+b] = (v,v), k = c*9+kh*3+kw ----
    #pragma unroll
    for (int idx = tid; idx < BATCH * KK; idx += NTHREADS) {
        const int b   = idx / KK;
        const int r   = idx - b * KK;     // r = (kh*3+kw)*64 + c  (c fastest: coalesced)
        const int khw = r >> 6;           // kh*3 + kw
        const int c   = r & 63;
        const int kh  = khw / 3;
        const int kw  = khw - kh * 3;
        const int k   = c * 9 + khw;      // feature index, C slowest
        const float v = x[(((b * H_IN) + h + kh) * W_IN + (wo + kw)) * C_IN + c];
        xs2[k * BATCH + b] = make_float2(v, v);
    }
    __syncthreads();

    // ---- Main loop: thread = (kslice, o4). Each weight float4 loaded once. ----
    const int o4 = tid & 15;    // 0..15 -> output float4 group
    const int ks = tid >> 4;    // 0..7  -> k slice
    // W row per k = 64 floats = 16 ulonglong2; take the o4-th 16B chunk.
    const ulonglong2* __restrict__ Wp =
        (const ulonglong2*)(w + (size_t)loc * (KK * C_OUT)) + o4;

    u64 acc01[BATCH], acc23[BATCH];
    #pragma unroll
    for (int b = 0; b < BATCH; ++b) { acc01[b] = 0ull; acc23[b] = 0ull; }

    const int kbeg = ks * KPS;
    #pragma unroll 4
    for (int k = kbeg; k < kbeg + KPS; ++k) {
        const ulonglong2 wv = Wp[k * 16];                 // LDG.128: (w01, w23)
        const ulonglong2* xp = (const ulonglong2*)(xs2 + k * BATCH);
        const ulonglong2 q0 = xp[0];   // (dup b0, dup b1)  LDS.128 broadcast
        const ulonglong2 q1 = xp[1];   // (dup b2, dup b3)
        const ulonglong2 q2 = xp[2];   // (dup b4, dup b5)
        const ulonglong2 q3 = xp[3];   // (dup b6, dup b7)
        acc01[0] = fma2(q0.x, wv.x, acc01[0]);  acc23[0] = fma2(q0.x, wv.y, acc23[0]);
        acc01[1] = fma2(q0.y, wv.x, acc01[1]);  acc23[1] = fma2(q0.y, wv.y, acc23[1]);
        acc01[2] = fma2(q1.x, wv.x, acc01[2]);  acc23[2] = fma2(q1.x, wv.y, acc23[2]);
        acc01[3] = fma2(q1.y, wv.x, acc01[3]);  acc23[3] = fma2(q1.y, wv.y, acc23[3]);
        acc01[4] = fma2(q2.x, wv.x, acc01[4]);  acc23[4] = fma2(q2.x, wv.y, acc23[4]);
        acc01[5] = fma2(q2.y, wv.x, acc01[5]);  acc23[5] = fma2(q2.y, wv.y, acc23[5]);
        acc01[6] = fma2(q3.x, wv.x, acc01[6]);  acc23[6] = fma2(q3.x, wv.y, acc23[6]);
        acc01[7] = fma2(q3.y, wv.x, acc01[7]);  acc23[7] = fma2(q3.y, wv.y, acc23[7]);
    }

    // ---- Reduce 8 k-slices through smem (aliased; row pad 9 kills conflicts) ----
    __syncthreads();   // everyone done reading xs2
    ulonglong2* red = (ulonglong2*)xs2;   // [NSLICE][16][9], 1152 * 16B = 18 KB
    #pragma unroll
    for (int b = 0; b < BATCH; ++b)
        red[(ks * 16 + o4) * 9 + b] = make_ulonglong2(acc01[b], acc23[b]);
    __syncthreads();

    const int b = tid >> 4;   // 0..7
    ulonglong2 s = red[o4 * 9 + b];
    #pragma unroll
    for (int sl = 1; sl < NSLICE; ++sl) {
        const ulonglong2 p = red[(sl * 16 + o4) * 9 + b];
        s.x = add2(s.x, p.x);
        s.y = add2(s.y, p.y);
    }

    ulonglong2* __restrict__ op =
        (ulonglong2*)(out + ((((size_t)b * H_OUT) + h) * W_OUT + wo) * C_OUT);
    op[o4] = s;
}

extern "C" void kernel_launch(void* const* d_in, const int* in_sizes, int n_in,
                              void* d_out, int out_size)
{
    const float* x  = (const float*)d_in[0];   // [8,32,32,64]
    const float* w  = (const float*)d_in[1];   // [30,30,576,64]
    float*       o  = (float*)d_out;           // [8,30,30,64]
    (void)in_sizes; (void)n_in; (void)out_size;

    lc_kernel<<<H_OUT * W_OUT, NTHREADS>>>(x, w, o);
}

// round 4
// speedup vs baseline: 1.1846x; 1.1846x over previous
#include <cuda_runtime.h>

// LocallyConnectedLinear: out[b,h,w,o] = sum_k xpatch[b,h,w,k] * W[h,w,k,o]
// x:  [8, 32, 32, 64]  f32   (NHWC)
// W:  [30, 30, 576, 64] f32  (k = c*9 + kh*3 + kw ; C slowest)
// out:[8, 30, 30, 64]  f32
//
// HBM-bound on the 132.7 MB weight stream (floor ~17us @ 8TB/s).
// R1: 53.7us (8x duplicated weight reads, L1-bound)
// R2: 31.2us (unique weight reads, DRAM 58%) — limited by 1-wave tail (~4us)
//     and 2-way LDS conflicts.
// R3: FFMA2 regressed (39.4us): doubled LDS traffic. Reverted.
// R4: grid 1800 (o split in 2 -> 2.03 waves, tiny tail), interleaved k slices
//     (conflict-free LDS, 4 consecutive full lines per warp LDG), unroll 6.

#define H_OUT 30
#define W_OUT 30
#define H_IN  32
#define W_IN  32
#define C_IN  64
#define C_OUT 64
#define KK    576   // 64 * 3 * 3
#define BATCH 8
#define NTHREADS 128
#define NSLICE 16   // k slices (interleaved: slice s owns k == s mod 16)
#define KPS    36   // KK / NSLICE
#define NO4    8    // float4 output groups per CTA (32 channels = half of 64)

__device__ __forceinline__ void fma4(float4& a, float s, const float4& w) {
    a.x += s * w.x; a.y += s * w.y; a.z += s * w.z; a.w += s * w.w;
}

__global__ __launch_bounds__(NTHREADS, 6)
void lc_kernel(const float* __restrict__ x,
               const float* __restrict__ w,
               float* __restrict__ out)
{
    // Phase 1: xs[k][b], KK x 8 floats = 18 KB.
    // Phase 2 (aliased): red[slice][o4][b] float4 with b-row pad 9:
    //   16 * 8 * 9 = 1152 float4 = 18 KB (exactly fits).
    __shared__ __align__(16) float smem[KK * BATCH];

    const int bid = blockIdx.x;          // 0..1799
    const int loc = bid >> 1;            // 0..899
    const int oh  = bid & 1;             // output half: channels [oh*32, oh*32+32)
    const int h   = loc / W_OUT;
    const int wo  = loc - h * W_OUT;
    const int tid = threadIdx.x;

    // ---- Stage im2col patch: xs[k][b], k = c*9 + kh*3 + kw (c fastest: coalesced) ----
    #pragma unroll
    for (int idx = tid; idx < BATCH * KK; idx += NTHREADS) {
        const int b   = idx / KK;
        const int r   = idx - b * KK;     // r = (kh*3+kw)*64 + c
        const int khw = r >> 6;           // kh*3 + kw
        const int c   = r & 63;
        const int kh  = khw / 3;
        const int kw  = khw - kh * 3;
        const int k   = c * 9 + khw;      // feature index, C slowest
        smem[k * BATCH + b] =
            x[(((b * H_IN) + h + kh) * W_IN + (wo + kw)) * C_IN + c];
    }
    __syncthreads();

    // ---- Main loop: thread = (ks, o4); slice ks owns k = ks, ks+16, ks+32, ...
    // Warp = 4 consecutive ks x 8 o4:
    //   LDG: 4 consecutive k rows, 128B (full aligned line) each -> 4 lines/warp.
    //   LDS: 4 addresses 32B apart -> conflict-free.
    const int o4 = tid & (NO4 - 1);   // 0..7
    const int ks = tid >> 3;          // 0..15
    const float4* __restrict__ Wp =
        (const float4*)(w + (size_t)loc * (KK * C_OUT)) + oh * 8 + o4;  // [KK][16]

    float4 acc[BATCH];
    #pragma unroll
    for (int b = 0; b < BATCH; ++b) acc[b] = make_float4(0.f, 0.f, 0.f, 0.f);

    #pragma unroll 6
    for (int j = 0; j < KPS; ++j) {
        const int k = ks + j * NSLICE;
        const float4 wv  = Wp[k * (C_OUT / 4)];                 // unique LDG.128
        const float4 xlo = *(const float4*)&smem[k * BATCH];    // LDS.128
        const float4 xhi = *(const float4*)&smem[k * BATCH + 4];
        fma4(acc[0], xlo.x, wv);
        fma4(acc[1], xlo.y, wv);
        fma4(acc[2], xlo.z, wv);
        fma4(acc[3], xlo.w, wv);
        fma4(acc[4], xhi.x, wv);
        fma4(acc[5], xhi.y, wv);
        fma4(acc[6], xhi.z, wv);
        fma4(acc[7], xhi.w, wv);
    }

    // ---- Reduce 16 k-slices through smem (aliased) ----
    __syncthreads();   // everyone done reading xs
    float4* red = (float4*)smem;   // [NSLICE][NO4][9]
    #pragma unroll
    for (int b = 0; b < BATCH; ++b)
        red[(ks * NO4 + o4) * 9 + b] = acc[b];
    __syncthreads();

    if (tid < NO4 * BATCH) {                 // 64 threads finish
        const int fo4 = tid & (NO4 - 1);     // 0..7
        const int b   = tid >> 3;            // 0..7
        float4 s = red[(fo4) * 9 + b];
        #pragma unroll
        for (int sl = 1; sl < NSLICE; ++sl) {
            const float4 p = red[(sl * NO4 + fo4) * 9 + b];
            s.x += p.x; s.y += p.y; s.z += p.z; s.w += p.w;
        }
        float4* __restrict__ op =
            (float4*)(out + ((((size_t)b * H_OUT) + h) * W_OUT + wo) * C_OUT)
            + oh * 8 + fo4;
        *op = s;
    }
}

extern "C" void kernel_launch(void* const* d_in, const int* in_sizes, int n_in,
                              void* d_out, int out_size)
{
    const float* x  = (const float*)d_in[0];   // [8,32,32,64]
    const float* w  = (const float*)d_in[1];   // [30,30,576,64]
    float*       o  = (float*)d_out;           // [8,30,30,64]
    (void)in_sizes; (void)n_in; (void)out_size;

    lc_kernel<<<H_OUT * W_OUT * 2, NTHREADS>>>(x, w, o);
}